// round 7
// baseline (speedup 1.0000x reference)
#include <cuda_runtime.h>

// ---------------------------------------------------------------------------
// SNNConvNet: conv1+relu+pool -> conv2+relu+pool -> fc1 -> 10-step LIF loop
// All fp32. Reduction-order strategy:
//  - convs: per-output chain over (ky, kx, c) ascending, c fastest (NHWC
//    im2col order), bias added AFTER the full sum.
//  - fc1: CHUNKED accumulation, 4 contiguous chunks of K=1024; each chunk a
//    strict ascending-k FMA chain; partials combined ((p0+p1)+p2)+p3, then
//    bias. (Eigen kc=1024 on 64KB-L1 Grace == cublasLt split-k=4 fixup.)
// ---------------------------------------------------------------------------

__device__ float g_h1[512 * 32 * 16 * 16];   // conv1 output (pooled)
__device__ float g_h2[512 * 4096];           // conv2 output (pooled, flattened)
__device__ float g_cur1[512 * 1000];         // fc1 output

// ============================ conv1 + relu + pool ==========================
__global__ __launch_bounds__(256) void conv1_kernel(
    const float* __restrict__ x, const float* __restrict__ w,
    const float* __restrict__ bias) {
  __shared__ float s_in[3 * 34 * 34];
  __shared__ float s_w[32 * 27];
  __shared__ float s_b[32];
  int img = blockIdx.x, tid = threadIdx.x;
  for (int i = tid; i < 3 * 34 * 34; i += 256) s_in[i] = 0.f;
  for (int i = tid; i < 32 * 27; i += 256) s_w[i] = w[i];
  if (tid < 32) s_b[tid] = bias[tid];
  __syncthreads();
  const float* xin = x + img * 3072;
  for (int i = tid; i < 3072; i += 256) {
    int c = i >> 10, rem = i & 1023, y = rem >> 5, xx = rem & 31;
    s_in[c * 1156 + (y + 1) * 34 + (xx + 1)] = xin[i];
  }
  __syncthreads();

  int py = tid >> 4, px = tid & 15;
  float r[3][4][4];
#pragma unroll
  for (int c = 0; c < 3; c++)
#pragma unroll
    for (int dy = 0; dy < 4; dy++)
#pragma unroll
      for (int dx = 0; dx < 4; dx++)
        r[c][dy][dx] = s_in[c * 1156 + (2 * py + dy) * 34 + (2 * px + dx)];

  float* outp = g_h1 + img * 8192 + py * 16 + px;
  for (int oc = 0; oc < 32; oc++) {
    float a00 = 0.f, a01 = 0.f, a10 = 0.f, a11 = 0.f;
    const float* wp = s_w + oc * 27;
#pragma unroll
    for (int ky = 0; ky < 3; ky++)
#pragma unroll
      for (int kx = 0; kx < 3; kx++)
#pragma unroll
        for (int c = 0; c < 3; c++) {     // c fastest (NHWC k-order)
          float wv = wp[c * 9 + ky * 3 + kx];
          a00 = fmaf(wv, r[c][ky][kx], a00);
          a01 = fmaf(wv, r[c][ky][kx + 1], a01);
          a10 = fmaf(wv, r[c][ky + 1][kx], a10);
          a11 = fmaf(wv, r[c][ky + 1][kx + 1], a11);
        }
    float bv = s_b[oc];
    a00 = __fadd_rn(a00, bv); a01 = __fadd_rn(a01, bv);
    a10 = __fadd_rn(a10, bv); a11 = __fadd_rn(a11, bv);
    float m = fmaxf(fmaxf(a00, a01), fmaxf(a10, a11));
    outp[oc * 256] = fmaxf(m, 0.f);
  }
}

// ============================ conv2 + relu + pool ==========================
__global__ __launch_bounds__(256) void conv2_kernel(
    const float* __restrict__ w, const float* __restrict__ bias) {
  extern __shared__ float sm[];
  float* s_in = sm;              // 32*18*18 = 10368 floats
  float* s_w = sm + 10368;       // 64*32*9  = 18432 floats
  float* s_b = s_w + 18432;      // 64 floats
  int img = blockIdx.x, tid = threadIdx.x;
  for (int i = tid; i < 10368; i += 256) s_in[i] = 0.f;
  for (int i = tid; i < 18432; i += 256) s_w[i] = w[i];
  if (tid < 64) s_b[tid] = bias[tid];
  __syncthreads();
  const float* hin = g_h1 + img * 8192;
  for (int i = tid; i < 8192; i += 256) {
    int c = i >> 8, rem = i & 255, y = rem >> 4, xx = rem & 15;
    s_in[c * 324 + (y + 1) * 18 + (xx + 1)] = hin[i];
  }
  __syncthreads();

  int pos = tid & 63, ocg = tid >> 6;
  int py = pos >> 3, px = pos & 7;
  int base_in = (2 * py) * 18 + 2 * px;
#pragma unroll 1
  for (int p = 0; p < 2; p++) {
    float acc[8][4];
#pragma unroll
    for (int i = 0; i < 8; i++) {
      acc[i][0] = 0.f; acc[i][1] = 0.f; acc[i][2] = 0.f; acc[i][3] = 0.f;
    }
#pragma unroll
    for (int ky = 0; ky < 3; ky++) {
#pragma unroll
      for (int kx = 0; kx < 3; kx++) {
        int ib = base_in + ky * 18 + kx;
        int wb = ky * 3 + kx;
#pragma unroll 4
        for (int c = 0; c < 32; c++) {     // c fastest (NHWC k-order)
          const float* ip = s_in + c * 324 + ib;
          float i00 = ip[0], i01 = ip[1], i10 = ip[18], i11 = ip[19];
          const float* wp = s_w + ((ocg * 16 + p * 8) * 32 + c) * 9 + wb;
#pragma unroll
          for (int i = 0; i < 8; i++) {
            float wv = wp[i * 288];        // (oc+1) advances by 32*9 floats
            acc[i][0] = fmaf(wv, i00, acc[i][0]);
            acc[i][1] = fmaf(wv, i01, acc[i][1]);
            acc[i][2] = fmaf(wv, i10, acc[i][2]);
            acc[i][3] = fmaf(wv, i11, acc[i][3]);
          }
        }
      }
    }
    float* op = g_h2 + img * 4096 + py * 8 + px;
#pragma unroll
    for (int i = 0; i < 8; i++) {
      int oc = ocg * 16 + p * 8 + i;
      float bv = s_b[oc];
      float v0 = __fadd_rn(acc[i][0], bv), v1 = __fadd_rn(acc[i][1], bv);
      float v2 = __fadd_rn(acc[i][2], bv), v3 = __fadd_rn(acc[i][3], bv);
      float m = fmaxf(fmaxf(v0, v1), fmaxf(v2, v3));
      op[oc * 64] = fmaxf(m, 0.f);
    }
  }
}

// ================================= fc1 GEMM ================================
// C[512,1000] = g_h2[512,4096] @ fc1_w[1000,4096]^T + bias
// CHUNKED reduction: K split into 4 contiguous chunks of 1024; each chunk a
// strict ascending-k FMA chain into `acc`; chunk partials folded into `tot`
// sequentially (((p0+p1)+p2)+p3); bias added last.
__global__ __launch_bounds__(256) void fc1_kernel(
    const float* __restrict__ Bw, const float* __restrict__ bias) {
  __shared__ float As[2][16][64];
  __shared__ float Bs[2][16][64];
  int tid = threadIdx.x;
  int m0 = blockIdx.y * 64, n0 = blockIdx.x * 64;
  int tx = tid & 15, ty = tid >> 4;
  int lrow = tid >> 2, lk4 = (tid & 3) * 4;

  const float* aP = g_h2 + (m0 + lrow) * 4096 + lk4;
  int brow = n0 + lrow; if (brow > 999) brow = 999;
  const float* bP = Bw + brow * 4096 + lk4;

  float4 aR = *(const float4*)aP;
  float4 bR = *(const float4*)bP;
  As[0][lk4 + 0][lrow] = aR.x; As[0][lk4 + 1][lrow] = aR.y;
  As[0][lk4 + 2][lrow] = aR.z; As[0][lk4 + 3][lrow] = aR.w;
  Bs[0][lk4 + 0][lrow] = bR.x; Bs[0][lk4 + 1][lrow] = bR.y;
  Bs[0][lk4 + 2][lrow] = bR.z; Bs[0][lk4 + 3][lrow] = bR.w;
  __syncthreads();

  float acc[4][4], tot[4][4];
#pragma unroll
  for (int i = 0; i < 4; i++)
#pragma unroll
    for (int j = 0; j < 4; j++) { acc[i][j] = 0.f; tot[i][j] = 0.f; }

#pragma unroll 1
  for (int ch = 0; ch < 256; ch++) {
    int buf = ch & 1;
    if (ch < 255) {
      aR = *(const float4*)(aP + (ch + 1) * 16);
      bR = *(const float4*)(bP + (ch + 1) * 16);
    }
#pragma unroll
    for (int k = 0; k < 16; k++) {
      float4 a4 = *(const float4*)&As[buf][k][ty * 4];
      float4 b4 = *(const float4*)&Bs[buf][k][tx * 4];
      acc[0][0] = fmaf(a4.x, b4.x, acc[0][0]); acc[0][1] = fmaf(a4.x, b4.y, acc[0][1]);
      acc[0][2] = fmaf(a4.x, b4.z, acc[0][2]); acc[0][3] = fmaf(a4.x, b4.w, acc[0][3]);
      acc[1][0] = fmaf(a4.y, b4.x, acc[1][0]); acc[1][1] = fmaf(a4.y, b4.y, acc[1][1]);
      acc[1][2] = fmaf(a4.y, b4.z, acc[1][2]); acc[1][3] = fmaf(a4.y, b4.w, acc[1][3]);
      acc[2][0] = fmaf(a4.z, b4.x, acc[2][0]); acc[2][1] = fmaf(a4.z, b4.y, acc[2][1]);
      acc[2][2] = fmaf(a4.z, b4.z, acc[2][2]); acc[2][3] = fmaf(a4.z, b4.w, acc[2][3]);
      acc[3][0] = fmaf(a4.w, b4.x, acc[3][0]); acc[3][1] = fmaf(a4.w, b4.y, acc[3][1]);
      acc[3][2] = fmaf(a4.w, b4.z, acc[3][2]); acc[3][3] = fmaf(a4.w, b4.w, acc[3][3]);
    }
    // chunk boundary every 64 K-chunks (1024 k's): fold partial, reset
    if ((ch & 63) == 63) {
#pragma unroll
      for (int i = 0; i < 4; i++)
#pragma unroll
        for (int j = 0; j < 4; j++) {
          tot[i][j] = __fadd_rn(tot[i][j], acc[i][j]);
          acc[i][j] = 0.f;
        }
    }
    if (ch < 255) {
      int nb = buf ^ 1;
      As[nb][lk4 + 0][lrow] = aR.x; As[nb][lk4 + 1][lrow] = aR.y;
      As[nb][lk4 + 2][lrow] = aR.z; As[nb][lk4 + 3][lrow] = aR.w;
      Bs[nb][lk4 + 0][lrow] = bR.x; Bs[nb][lk4 + 1][lrow] = bR.y;
      Bs[nb][lk4 + 2][lrow] = bR.z; Bs[nb][lk4 + 3][lrow] = bR.w;
      __syncthreads();
    }
  }

  float bv[4];
#pragma unroll
  for (int j = 0; j < 4; j++) {
    int n = n0 + tx * 4 + j;
    bv[j] = (n < 1000) ? bias[n] : 0.f;
  }
#pragma unroll
  for (int i = 0; i < 4; i++) {
    int m = m0 + ty * 4 + i;
#pragma unroll
    for (int j = 0; j < 4; j++) {
      int n = n0 + tx * 4 + j;
      if (n < 1000) g_cur1[m * 1000 + n] = __fadd_rn(tot[i][j], bv[j]);
    }
  }
}

// ============================ fused 10-step LIF ============================
// Output layout: [ spk2_rec[10,512,10] | mem2_rec[10,512,10] ].
__global__ __launch_bounds__(256) void snn_kernel(
    const float* __restrict__ fc2_w, const float* __restrict__ fc2_b,
    float* __restrict__ out) {
  __shared__ float s_w[10000];
  __shared__ float s_b[10];
  __shared__ float s_ws[4][2][10];
  int tid = threadIdx.x;
  for (int i = tid; i < 10000; i += 256) s_w[i] = fc2_w[i];
  if (tid < 10) s_b[tid] = fc2_b[tid];

  int r = tid >> 6, lane64 = tid & 63;
  int b = blockIdx.x * 4 + r;
  int half = (tid >> 5) & 1;

  float m1[16], c1[16];
#pragma unroll
  for (int u = 0; u < 16; u++) {
    int j = lane64 + 64 * u;
    c1[u] = (j < 1000) ? g_cur1[b * 1000 + j] : 0.f;
    m1[u] = 0.f;
  }
  float mem2 = 0.f;
  __syncthreads();

  for (int t = 0; t < 10; t++) {
    float acc[10];
#pragma unroll
    for (int k = 0; k < 10; k++) acc[k] = 0.f;
#pragma unroll
    for (int u = 0; u < 16; u++) {
      int j = lane64 + 64 * u;
      // snnTorch Leaky: subtract-reset from PREVIOUS mem, then new spike
      float reset = (m1[u] > 1.0f) ? 1.0f : 0.0f;
      float nm = 0.95f * m1[u] + c1[u] - reset;
      m1[u] = nm;
      if (j < 1000 && nm > 1.0f) {
#pragma unroll
        for (int k = 0; k < 10; k++) acc[k] += s_w[k * 1000 + j];
      }
    }
    // reduce 64 threads (2 warps) per row
#pragma unroll
    for (int k = 0; k < 10; k++) {
      float v = acc[k];
      v += __shfl_down_sync(0xffffffffu, v, 16);
      v += __shfl_down_sync(0xffffffffu, v, 8);
      v += __shfl_down_sync(0xffffffffu, v, 4);
      v += __shfl_down_sync(0xffffffffu, v, 2);
      v += __shfl_down_sync(0xffffffffu, v, 1);
      acc[k] = v;
    }
    if ((tid & 31) == 0) {
#pragma unroll
      for (int k = 0; k < 10; k++) s_ws[r][half][k] = acc[k];
    }
    __syncthreads();
    if (lane64 < 10) {
      int k = lane64;
      float cur2 = (s_ws[r][0][k] + s_ws[r][1][k]) + s_b[k];
      float reset2 = (mem2 > 1.0f) ? 1.0f : 0.0f;
      float nm2 = 0.95f * mem2 + cur2 - reset2;
      mem2 = nm2;
      float spk2 = (nm2 > 1.0f) ? 1.0f : 0.0f;
      out[t * 5120 + b * 10 + k] = spk2;
      out[51200 + t * 5120 + b * 10 + k] = nm2;
    }
    __syncthreads();
  }
}

// ================================= launcher ================================
extern "C" void kernel_launch(void* const* d_in, const int* in_sizes, int n_in,
                              void* d_out, int out_size) {
  const float* x   = (const float*)d_in[0];
  const float* c1w = (const float*)d_in[1];
  const float* c1b = (const float*)d_in[2];
  const float* c2w = (const float*)d_in[3];
  const float* c2b = (const float*)d_in[4];
  const float* f1w = (const float*)d_in[5];
  const float* f1b = (const float*)d_in[6];
  const float* f2w = (const float*)d_in[7];
  const float* f2b = (const float*)d_in[8];
  float* out = (float*)d_out;

  cudaFuncSetAttribute(conv2_kernel,
                       cudaFuncAttributeMaxDynamicSharedMemorySize, 115456);

  conv1_kernel<<<512, 256>>>(x, c1w, c1b);
  conv2_kernel<<<512, 256, 115456>>>(c2w, c2b);
  fc1_kernel<<<dim3(16, 8), 256>>>(f1w, f1b);
  snn_kernel<<<128, 256>>>(f2w, f2b, out);
}

// round 8
// speedup vs baseline: 1.1199x; 1.1199x over previous
#include <cuda_runtime.h>

// ---------------------------------------------------------------------------
// SNNConvNet. fp32; reduction orders FROZEN (they bit-match the reference):
//  - convs: per-output chain over (ky,kx) outer, c inner ascending; bias after.
//  - fc1: 4 contiguous K-chunks of 1024, each a strict ascending-k chain;
//    partials combined ((p0+p1)+p2)+p3 then +bias (done in snn preamble).
// This round: LDS:FMA-balanced tilings + split-k parallelism, same arithmetic.
// ---------------------------------------------------------------------------

__device__ float g_h1[512 * 32 * 16 * 16];   // conv1 output (pooled)
__device__ float g_h2[512 * 4096];           // conv2 output (pooled, flattened)
__device__ float g_fc1p[4][512 * 1000];      // fc1 per-chunk partials

// ============================ conv1 + relu + pool ==========================
__global__ __launch_bounds__(256) void conv1_kernel(
    const float* __restrict__ x, const float* __restrict__ w,
    const float* __restrict__ bias) {
  __shared__ float s_in[3 * 34 * 34];
  __shared__ float s_w[32 * 27];
  __shared__ float s_b[32];
  int img = blockIdx.x, tid = threadIdx.x;
  for (int i = tid; i < 3 * 34 * 34; i += 256) s_in[i] = 0.f;
  for (int i = tid; i < 32 * 27; i += 256) s_w[i] = w[i];
  if (tid < 32) s_b[tid] = bias[tid];
  __syncthreads();
  const float* xin = x + img * 3072;
  for (int i = tid; i < 3072; i += 256) {
    int c = i >> 10, rem = i & 1023, y = rem >> 5, xx = rem & 31;
    s_in[c * 1156 + (y + 1) * 34 + (xx + 1)] = xin[i];
  }
  __syncthreads();

  int py = tid >> 4, px = tid & 15;
  float r[3][4][4];
#pragma unroll
  for (int c = 0; c < 3; c++)
#pragma unroll
    for (int dy = 0; dy < 4; dy++)
#pragma unroll
      for (int dx = 0; dx < 4; dx++)
        r[c][dy][dx] = s_in[c * 1156 + (2 * py + dy) * 34 + (2 * px + dx)];

  float* outp = g_h1 + img * 8192 + py * 16 + px;
  for (int oc = 0; oc < 32; oc++) {
    float a00 = 0.f, a01 = 0.f, a10 = 0.f, a11 = 0.f;
    const float* wp = s_w + oc * 27;
#pragma unroll
    for (int ky = 0; ky < 3; ky++)
#pragma unroll
      for (int kx = 0; kx < 3; kx++)
#pragma unroll
        for (int c = 0; c < 3; c++) {     // c fastest (frozen k-order)
          float wv = wp[c * 9 + ky * 3 + kx];
          a00 = fmaf(wv, r[c][ky][kx], a00);
          a01 = fmaf(wv, r[c][ky][kx + 1], a01);
          a10 = fmaf(wv, r[c][ky + 1][kx], a10);
          a11 = fmaf(wv, r[c][ky + 1][kx + 1], a11);
        }
    float bv = s_b[oc];
    a00 = __fadd_rn(a00, bv); a01 = __fadd_rn(a01, bv);
    a10 = __fadd_rn(a10, bv); a11 = __fadd_rn(a11, bv);
    float m = fmaxf(fmaxf(a00, a01), fmaxf(a10, a11));
    outp[oc * 256] = fmaxf(m, 0.f);
  }
}

// ============================ conv2 + relu + pool ==========================
// Thread = 8 output channels x 2 adjacent pooled outputs (8 conv positions).
// Per (ky,kx,c): 8 input + 8 weight LDS for 64 FMA -> LDS:FMA balanced.
// Chain per output unchanged: (ky,kx) outer, c inner ascending; bias after.
__global__ __launch_bounds__(256) void conv2_kernel(
    const float* __restrict__ w, const float* __restrict__ bias) {
  extern __shared__ float sm[];
  float* s_in = sm;              // 32*18*18 = 10368 floats
  float* s_w = sm + 10368;       // 64*32*9  = 18432 floats
  float* s_b = s_w + 18432;      // 64 floats
  int img = blockIdx.x, tid = threadIdx.x;
  for (int i = tid; i < 10368; i += 256) s_in[i] = 0.f;
  for (int i = tid; i < 18432; i += 256) s_w[i] = w[i];
  if (tid < 64) s_b[tid] = bias[tid];
  __syncthreads();
  const float* hin = g_h1 + img * 8192;
  for (int i = tid; i < 8192; i += 256) {
    int c = i >> 8, rem = i & 255, y = rem >> 4, xx = rem & 15;
    s_in[c * 324 + (y + 1) * 18 + (xx + 1)] = hin[i];
  }
  __syncthreads();

  int pg = tid & 31, ocg = tid >> 5;       // 32 pos-groups x 8 oc-groups
  int py = pg >> 2, pxp = pg & 3;          // pooled row, pooled-col pair
  // acc[i][s]: s = p*4 + dy*2 + dx for pooled p in {0,1}
  float acc[8][8];
#pragma unroll
  for (int i = 0; i < 8; i++)
#pragma unroll
    for (int s = 0; s < 8; s++) acc[i][s] = 0.f;

#pragma unroll
  for (int ky = 0; ky < 3; ky++) {
#pragma unroll
    for (int kx = 0; kx < 3; kx++) {
      int ib = (2 * py + ky) * 18 + 4 * pxp + kx;
      int wb = ky * 3 + kx;
#pragma unroll 2
      for (int c = 0; c < 32; c++) {       // c fastest (frozen k-order)
        const float* ip = s_in + c * 324 + ib;
        float i0 = ip[0], i1 = ip[1], i2 = ip[2], i3 = ip[3];
        float i4 = ip[18], i5 = ip[19], i6 = ip[20], i7 = ip[21];
        const float* wp = s_w + (ocg * 8 * 32 + c) * 9 + wb;
#pragma unroll
        for (int i = 0; i < 8; i++) {
          float wv = wp[i * 288];
          acc[i][0] = fmaf(wv, i0, acc[i][0]);  // p0 dy0 dx0
          acc[i][1] = fmaf(wv, i1, acc[i][1]);  // p0 dy0 dx1
          acc[i][2] = fmaf(wv, i4, acc[i][2]);  // p0 dy1 dx0
          acc[i][3] = fmaf(wv, i5, acc[i][3]);  // p0 dy1 dx1
          acc[i][4] = fmaf(wv, i2, acc[i][4]);  // p1 dy0 dx0
          acc[i][5] = fmaf(wv, i3, acc[i][5]);  // p1 dy0 dx1
          acc[i][6] = fmaf(wv, i6, acc[i][6]);  // p1 dy1 dx0
          acc[i][7] = fmaf(wv, i7, acc[i][7]);  // p1 dy1 dx1
        }
      }
    }
  }

  float* op = g_h2 + img * 4096 + py * 8 + 2 * pxp;
#pragma unroll
  for (int i = 0; i < 8; i++) {
    int oc = ocg * 8 + i;
    float bv = s_b[oc];
#pragma unroll
    for (int p = 0; p < 2; p++) {
      float v0 = __fadd_rn(acc[i][p * 4 + 0], bv);
      float v1 = __fadd_rn(acc[i][p * 4 + 1], bv);
      float v2 = __fadd_rn(acc[i][p * 4 + 2], bv);
      float v3 = __fadd_rn(acc[i][p * 4 + 3], bv);
      float m = fmaxf(fmaxf(v0, v1), fmaxf(v2, v3));
      op[oc * 64 + p] = fmaxf(m, 0.f);
    }
  }
}

// ================================= fc1 GEMM ================================
// Partial[z][512,1000] = g_h2[:, z*1024:(z+1)*1024] @ fc1_w[:, same]^T
// grid (8,4,4): 128x128 tile, 8x8 micro-tile, one 1024-chunk per z-block.
// Per output: single accumulator, strict ascending-k chain (frozen order).
__global__ __launch_bounds__(256) void fc1_kernel(const float* __restrict__ Bw) {
  __shared__ float As[2][16][128];
  __shared__ float Bs[2][16][128];
  int tid = threadIdx.x;
  int m0 = blockIdx.y * 128, n0 = blockIdx.x * 128, z = blockIdx.z;
  int tx = tid & 15, ty = tid >> 4;
  int lrow = tid & 127, lk8 = (tid >> 7) * 8;   // conflict-free smem stores

  const float* aP = g_h2 + (m0 + lrow) * 4096 + z * 1024 + lk8;
  int brow = n0 + lrow; if (brow > 999) brow = 999;
  const float* bP = Bw + brow * 4096 + z * 1024 + lk8;

  float4 a0 = *(const float4*)aP, a1 = *(const float4*)(aP + 4);
  float4 b0 = *(const float4*)bP, b1 = *(const float4*)(bP + 4);
#pragma unroll
  for (int q = 0; q < 4; q++) {
    As[0][lk8 + q][lrow] = ((const float*)&a0)[q];
    As[0][lk8 + 4 + q][lrow] = ((const float*)&a1)[q];
    Bs[0][lk8 + q][lrow] = ((const float*)&b0)[q];
    Bs[0][lk8 + 4 + q][lrow] = ((const float*)&b1)[q];
  }
  __syncthreads();

  float acc[8][8];
#pragma unroll
  for (int i = 0; i < 8; i++)
#pragma unroll
    for (int j = 0; j < 8; j++) acc[i][j] = 0.f;

#pragma unroll 1
  for (int ch = 0; ch < 64; ch++) {
    int buf = ch & 1;
    if (ch < 63) {
      a0 = *(const float4*)(aP + (ch + 1) * 16);
      a1 = *(const float4*)(aP + (ch + 1) * 16 + 4);
      b0 = *(const float4*)(bP + (ch + 1) * 16);
      b1 = *(const float4*)(bP + (ch + 1) * 16 + 4);
    }
#pragma unroll
    for (int k = 0; k < 16; k++) {
      float4 af0 = *(const float4*)&As[buf][k][ty * 8];
      float4 af1 = *(const float4*)&As[buf][k][ty * 8 + 4];
      float4 bf0 = *(const float4*)&Bs[buf][k][tx * 8];
      float4 bf1 = *(const float4*)&Bs[buf][k][tx * 8 + 4];
      const float* av = (const float*)&af0;  // af0,af1 contiguous in regs? no-
      float am[8] = {af0.x, af0.y, af0.z, af0.w, af1.x, af1.y, af1.z, af1.w};
      float bm[8] = {bf0.x, bf0.y, bf0.z, bf0.w, bf1.x, bf1.y, bf1.z, bf1.w};
      (void)av;
#pragma unroll
      for (int i = 0; i < 8; i++)
#pragma unroll
        for (int j = 0; j < 8; j++)
          acc[i][j] = fmaf(am[i], bm[j], acc[i][j]);
    }
    if (ch < 63) {
      int nb = buf ^ 1;
#pragma unroll
      for (int q = 0; q < 4; q++) {
        As[nb][lk8 + q][lrow] = ((const float*)&a0)[q];
        As[nb][lk8 + 4 + q][lrow] = ((const float*)&a1)[q];
        Bs[nb][lk8 + q][lrow] = ((const float*)&b0)[q];
        Bs[nb][lk8 + 4 + q][lrow] = ((const float*)&b1)[q];
      }
      __syncthreads();
    }
  }

  float* outp = g_fc1p[z];
#pragma unroll
  for (int i = 0; i < 8; i++) {
    int m = m0 + ty * 8 + i;
#pragma unroll
    for (int j = 0; j < 8; j++) {
      int n = n0 + tx * 8 + j;
      if (n < 1000) outp[m * 1000 + n] = acc[i][j];
    }
  }
}

// ============================ fused 10-step LIF ============================
// Block = 2 batch rows x 128 threads/row (256 blocks). Preamble folds the 4
// fc1 chunk-partials ((p0+p1)+p2)+p3 + bias with frozen __fadd_rn ordering.
// Output layout: [ spk2_rec[10,512,10] | mem2_rec[10,512,10] ].
__global__ __launch_bounds__(256) void snn_kernel(
    const float* __restrict__ fc2_w, const float* __restrict__ fc2_b,
    const float* __restrict__ fc1_b, float* __restrict__ out) {
  __shared__ float s_w[10000];
  __shared__ float s_b[10];
  __shared__ float s_ws[2][4][10];
  int tid = threadIdx.x;
  for (int i = tid; i < 10000; i += 256) s_w[i] = fc2_w[i];
  if (tid < 10) s_b[tid] = fc2_b[tid];

  int r = tid >> 7, lane = tid & 127;
  int wip = (tid >> 5) & 3;              // warp index within row
  int b = blockIdx.x * 2 + r;

  const float* p0 = g_fc1p[0];
  const float* p1 = g_fc1p[1];
  const float* p2 = g_fc1p[2];
  const float* p3 = g_fc1p[3];

  float m1[8], c1[8];
#pragma unroll
  for (int u = 0; u < 8; u++) {
    int j = lane + 128 * u;
    if (j < 1000) {
      int idx = b * 1000 + j;
      float t = __fadd_rn(__fadd_rn(__fadd_rn(p0[idx], p1[idx]), p2[idx]),
                          p3[idx]);
      c1[u] = __fadd_rn(t, fc1_b[j]);
    } else {
      c1[u] = 0.f;
    }
    m1[u] = 0.f;
  }
  float mem2 = 0.f;
  __syncthreads();

  for (int t = 0; t < 10; t++) {
    float acc[10];
#pragma unroll
    for (int k = 0; k < 10; k++) acc[k] = 0.f;
#pragma unroll
    for (int u = 0; u < 8; u++) {
      int j = lane + 128 * u;
      // snnTorch Leaky: subtract-reset from PREVIOUS mem, then new spike
      float reset = (m1[u] > 1.0f) ? 1.0f : 0.0f;
      float nm = 0.95f * m1[u] + c1[u] - reset;
      m1[u] = nm;
      if (j < 1000 && nm > 1.0f) {
#pragma unroll
        for (int k = 0; k < 10; k++) acc[k] += s_w[k * 1000 + j];
      }
    }
#pragma unroll
    for (int k = 0; k < 10; k++) {
      float v = acc[k];
      v += __shfl_down_sync(0xffffffffu, v, 16);
      v += __shfl_down_sync(0xffffffffu, v, 8);
      v += __shfl_down_sync(0xffffffffu, v, 4);
      v += __shfl_down_sync(0xffffffffu, v, 2);
      v += __shfl_down_sync(0xffffffffu, v, 1);
      acc[k] = v;
    }
    if ((tid & 31) == 0) {
#pragma unroll
      for (int k = 0; k < 10; k++) s_ws[r][wip][k] = acc[k];
    }
    __syncthreads();
    if (lane < 10) {
      int k = lane;
      float cur2 = (((s_ws[r][0][k] + s_ws[r][1][k]) + s_ws[r][2][k]) +
                    s_ws[r][3][k]) + s_b[k];
      float reset2 = (mem2 > 1.0f) ? 1.0f : 0.0f;
      float nm2 = 0.95f * mem2 + cur2 - reset2;
      mem2 = nm2;
      float spk2 = (nm2 > 1.0f) ? 1.0f : 0.0f;
      out[t * 5120 + b * 10 + k] = spk2;
      out[51200 + t * 5120 + b * 10 + k] = nm2;
    }
    __syncthreads();
  }
}

// ================================= launcher ================================
extern "C" void kernel_launch(void* const* d_in, const int* in_sizes, int n_in,
                              void* d_out, int out_size) {
  const float* x   = (const float*)d_in[0];
  const float* c1w = (const float*)d_in[1];
  const float* c1b = (const float*)d_in[2];
  const float* c2w = (const float*)d_in[3];
  const float* c2b = (const float*)d_in[4];
  const float* f1w = (const float*)d_in[5];
  const float* f1b = (const float*)d_in[6];
  const float* f2w = (const float*)d_in[7];
  const float* f2b = (const float*)d_in[8];
  float* out = (float*)d_out;

  cudaFuncSetAttribute(conv2_kernel,
                       cudaFuncAttributeMaxDynamicSharedMemorySize, 115456);

  conv1_kernel<<<512, 256>>>(x, c1w, c1b);
  conv2_kernel<<<512, 256, 115456>>>(c2w, c2b);
  fc1_kernel<<<dim3(8, 4, 4), 256>>>(f1w);
  snn_kernel<<<256, 256>>>(f2w, f2b, f1b, out);
}

// round 10
// speedup vs baseline: 1.1486x; 1.0257x over previous
#include <cuda_runtime.h>

// ---------------------------------------------------------------------------
// SNNConvNet. fp32; reduction orders FROZEN (bit-match the reference):
//  - convs: per-output chain over (ky,kx) outer, c inner ascending; bias after.
//  - fc1: 4 contiguous K-chunks of 1024, each strict ascending-k; partials
//    combined ((p0+p1)+p2)+p3 + bias in snn preamble.
// This round: packed fma.rn.f32x2 (FFMA2) in fc1/conv2 inner loops — two
// IEEE-rn fp32 FMAs per instruction, per-lane rounding identical to scalar.
// ---------------------------------------------------------------------------

typedef unsigned long long u64;

__device__ __forceinline__ u64 pack2(float lo, float hi) {
  u64 r; asm("mov.b64 %0, {%1, %2};" : "=l"(r) : "f"(lo), "f"(hi)); return r;
}
__device__ __forceinline__ u64 dup2(float v) {
  u64 r; asm("mov.b64 %0, {%1, %1};" : "=l"(r) : "f"(v)); return r;
}
__device__ __forceinline__ void ffma2(u64& d, u64 a, u64 b) {
  asm("fma.rn.f32x2 %0, %1, %2, %0;" : "+l"(d) : "l"(a), "l"(b));
}
__device__ __forceinline__ void unpack2(u64 v, float& lo, float& hi) {
  asm("mov.b64 {%0, %1}, %2;" : "=f"(lo), "=f"(hi) : "l"(v));
}

__device__ float g_h1[512 * 32 * 16 * 16];   // conv1 output (pooled)
__device__ float g_h2[512 * 4096];           // conv2 output (pooled, flattened)
__device__ float g_fc1p[4][512 * 1000];      // fc1 per-chunk partials

// ============================ conv1 + relu + pool ==========================
__global__ __launch_bounds__(256) void conv1_kernel(
    const float* __restrict__ x, const float* __restrict__ w,
    const float* __restrict__ bias) {
  __shared__ float s_in[3 * 34 * 34];
  __shared__ float s_w[32 * 27];
  __shared__ float s_b[32];
  int img = blockIdx.x, tid = threadIdx.x;
  for (int i = tid; i < 3 * 34 * 34; i += 256) s_in[i] = 0.f;
  for (int i = tid; i < 32 * 27; i += 256) s_w[i] = w[i];
  if (tid < 32) s_b[tid] = bias[tid];
  __syncthreads();
  const float* xin = x + img * 3072;
  for (int i = tid; i < 3072; i += 256) {
    int c = i >> 10, rem = i & 1023, y = rem >> 5, xx = rem & 31;
    s_in[c * 1156 + (y + 1) * 34 + (xx + 1)] = xin[i];
  }
  __syncthreads();

  int py = tid >> 4, px = tid & 15;
  float r[3][4][4];
#pragma unroll
  for (int c = 0; c < 3; c++)
#pragma unroll
    for (int dy = 0; dy < 4; dy++)
#pragma unroll
      for (int dx = 0; dx < 4; dx++)
        r[c][dy][dx] = s_in[c * 1156 + (2 * py + dy) * 34 + (2 * px + dx)];

  float* outp = g_h1 + img * 8192 + py * 16 + px;
  for (int oc = 0; oc < 32; oc++) {
    float a00 = 0.f, a01 = 0.f, a10 = 0.f, a11 = 0.f;
    const float* wp = s_w + oc * 27;
#pragma unroll
    for (int ky = 0; ky < 3; ky++)
#pragma unroll
      for (int kx = 0; kx < 3; kx++)
#pragma unroll
        for (int c = 0; c < 3; c++) {     // c fastest (frozen k-order)
          float wv = wp[c * 9 + ky * 3 + kx];
          a00 = fmaf(wv, r[c][ky][kx], a00);
          a01 = fmaf(wv, r[c][ky][kx + 1], a01);
          a10 = fmaf(wv, r[c][ky + 1][kx], a10);
          a11 = fmaf(wv, r[c][ky + 1][kx + 1], a11);
        }
    float bv = s_b[oc];
    a00 = __fadd_rn(a00, bv); a01 = __fadd_rn(a01, bv);
    a10 = __fadd_rn(a10, bv); a11 = __fadd_rn(a11, bv);
    float m = fmaxf(fmaxf(a00, a01), fmaxf(a10, a11));
    outp[oc * 256] = fmaxf(m, 0.f);
  }
}

// ============================ conv2 + relu + pool ==========================
// Thread = 8 oc x 8 conv positions (2 pooled outputs), FFMA2-packed over
// position pairs. Chain per output unchanged: (ky,kx) outer, c inner.
__global__ __launch_bounds__(256) void conv2_kernel(
    const float* __restrict__ w, const float* __restrict__ bias) {
  extern __shared__ float sm[];
  float* s_in = sm;              // 32*18*18 = 10368 floats
  float* s_w = sm + 10368;       // 64*32*9  = 18432 floats
  float* s_b = s_w + 18432;      // 64 floats
  int img = blockIdx.x, tid = threadIdx.x;
  for (int i = tid; i < 10368; i += 256) s_in[i] = 0.f;
  for (int i = tid; i < 18432; i += 256) s_w[i] = w[i];
  if (tid < 64) s_b[tid] = bias[tid];
  __syncthreads();
  const float* hin = g_h1 + img * 8192;
  for (int i = tid; i < 8192; i += 256) {
    int c = i >> 8, rem = i & 255, y = rem >> 4, xx = rem & 15;
    s_in[c * 324 + (y + 1) * 18 + (xx + 1)] = hin[i];
  }
  __syncthreads();

  int pg = tid & 31, ocg = tid >> 5;       // 32 pos-groups x 8 oc-groups
  int py = pg >> 2, pxp = pg & 3;          // pooled row, pooled-col pair
  // acc2[i][sp]: sp pairs = (s0,s1)(s2,s3)(s4,s5)(s6,s7) of the original s
  u64 acc2[8][4];
#pragma unroll
  for (int i = 0; i < 8; i++)
#pragma unroll
    for (int sp = 0; sp < 4; sp++) acc2[i][sp] = 0ull;

#pragma unroll
  for (int ky = 0; ky < 3; ky++) {
#pragma unroll
    for (int kx = 0; kx < 3; kx++) {
      int ib = (2 * py + ky) * 18 + 4 * pxp + kx;
      int wb = ky * 3 + kx;
#pragma unroll 2
      for (int c = 0; c < 32; c++) {       // c fastest (frozen k-order)
        const float* ip = s_in + c * 324 + ib;
        u64 p01 = pack2(ip[0], ip[1]);      // (p0 dy0 dx0, p0 dy0 dx1)
        u64 p23 = pack2(ip[18], ip[19]);    // (p0 dy1 dx0, p0 dy1 dx1)
        u64 p45 = pack2(ip[2], ip[3]);      // (p1 dy0 dx0, p1 dy0 dx1)
        u64 p67 = pack2(ip[20], ip[21]);    // (p1 dy1 dx0, p1 dy1 dx1)
        const float* wp = s_w + (ocg * 8 * 32 + c) * 9 + wb;
#pragma unroll
        for (int i = 0; i < 8; i++) {
          u64 wd = dup2(wp[i * 288]);
          ffma2(acc2[i][0], wd, p01);
          ffma2(acc2[i][1], wd, p23);
          ffma2(acc2[i][2], wd, p45);
          ffma2(acc2[i][3], wd, p67);
        }
      }
    }
  }

  float* op = g_h2 + img * 4096 + py * 8 + 2 * pxp;
#pragma unroll
  for (int i = 0; i < 8; i++) {
    int oc = ocg * 8 + i;
    float bv = s_b[oc];
#pragma unroll
    for (int p = 0; p < 2; p++) {
      float v0, v1, v2, v3;
      unpack2(acc2[i][p * 2 + 0], v0, v1);
      unpack2(acc2[i][p * 2 + 1], v2, v3);
      v0 = __fadd_rn(v0, bv); v1 = __fadd_rn(v1, bv);
      v2 = __fadd_rn(v2, bv); v3 = __fadd_rn(v3, bv);
      float m = fmaxf(fmaxf(v0, v1), fmaxf(v2, v3));
      op[oc * 64 + p] = fmaxf(m, 0.f);
    }
  }
}

// ================================= fc1 GEMM ================================
// Partial[z][512,1000] = g_h2[:, z*1024:(z+1)*1024] @ fc1_w[:, same]^T
// grid (8,4,4): 128x128 tile, 8x8 micro-tile, FFMA2-packed over j-pairs.
// Per output: single accumulator, strict ascending-k chain (frozen order).
__global__ __launch_bounds__(256) void fc1_kernel(const float* __restrict__ Bw) {
  __shared__ float As[2][16][128];
  __shared__ float Bs[2][16][128];
  int tid = threadIdx.x;
  int m0 = blockIdx.y * 128, n0 = blockIdx.x * 128, z = blockIdx.z;
  int tx = tid & 15, ty = tid >> 4;
  int lrow = tid & 127, lk8 = (tid >> 7) * 8;

  const float* aP = g_h2 + (m0 + lrow) * 4096 + z * 1024 + lk8;
  int brow = n0 + lrow; if (brow > 999) brow = 999;
  const float* bP = Bw + brow * 4096 + z * 1024 + lk8;

  float4 a0 = *(const float4*)aP, a1 = *(const float4*)(aP + 4);
  float4 b0 = *(const float4*)bP, b1 = *(const float4*)(bP + 4);
#pragma unroll
  for (int q = 0; q < 4; q++) {
    As[0][lk8 + q][lrow] = ((const float*)&a0)[q];
    As[0][lk8 + 4 + q][lrow] = ((const float*)&a1)[q];
    Bs[0][lk8 + q][lrow] = ((const float*)&b0)[q];
    Bs[0][lk8 + 4 + q][lrow] = ((const float*)&b1)[q];
  }
  __syncthreads();

  u64 acc2[8][4];
#pragma unroll
  for (int i = 0; i < 8; i++)
#pragma unroll
    for (int jp = 0; jp < 4; jp++) acc2[i][jp] = 0ull;

#pragma unroll 1
  for (int ch = 0; ch < 64; ch++) {
    int buf = ch & 1;
    if (ch < 63) {
      a0 = *(const float4*)(aP + (ch + 1) * 16);
      a1 = *(const float4*)(aP + (ch + 1) * 16 + 4);
      b0 = *(const float4*)(bP + (ch + 1) * 16);
      b1 = *(const float4*)(bP + (ch + 1) * 16 + 4);
    }
#pragma unroll
    for (int k = 0; k < 16; k++) {
      float4 af0 = *(const float4*)&As[buf][k][ty * 8];
      float4 af1 = *(const float4*)&As[buf][k][ty * 8 + 4];
      // B as natural 64-bit pairs (j, j+1) straight from smem
      ulonglong2 bp0 = *(const ulonglong2*)&Bs[buf][k][tx * 8];
      ulonglong2 bp1 = *(const ulonglong2*)&Bs[buf][k][tx * 8 + 4];
      u64 b2[4] = {bp0.x, bp0.y, bp1.x, bp1.y};
      float am[8] = {af0.x, af0.y, af0.z, af0.w, af1.x, af1.y, af1.z, af1.w};
#pragma unroll
      for (int i = 0; i < 8; i++) {
        u64 ad = dup2(am[i]);
#pragma unroll
        for (int jp = 0; jp < 4; jp++) ffma2(acc2[i][jp], ad, b2[jp]);
      }
    }
    if (ch < 63) {
      int nb = buf ^ 1;
#pragma unroll
      for (int q = 0; q < 4; q++) {
        As[nb][lk8 + q][lrow] = ((const float*)&a0)[q];
        As[nb][lk8 + 4 + q][lrow] = ((const float*)&a1)[q];
        Bs[nb][lk8 + q][lrow] = ((const float*)&b0)[q];
        Bs[nb][lk8 + 4 + q][lrow] = ((const float*)&b1)[q];
      }
      __syncthreads();
    }
  }

  float* outp = g_fc1p[z];
#pragma unroll
  for (int i = 0; i < 8; i++) {
    int m = m0 + ty * 8 + i;
#pragma unroll
    for (int jp = 0; jp < 4; jp++) {
      float v0, v1;
      unpack2(acc2[i][jp], v0, v1);
      int n = n0 + tx * 8 + 2 * jp;
      if (n < 1000) outp[m * 1000 + n] = v0;
      if (n + 1 < 1000) outp[m * 1000 + n + 1] = v1;
    }
  }
}

// ============================ fused 10-step LIF ============================
// Block = 2 batch rows x 128 threads/row (256 blocks). Preamble folds the 4
// fc1 chunk-partials ((p0+p1)+p2)+p3 + bias with frozen __fadd_rn ordering.
// Output layout: [ spk2_rec[10,512,10] | mem2_rec[10,512,10] ].
__global__ __launch_bounds__(256) void snn_kernel(
    const float* __restrict__ fc2_w, const float* __restrict__ fc2_b,
    const float* __restrict__ fc1_b, float* __restrict__ out) {
  __shared__ float s_w[10000];
  __shared__ float s_b[10];
  __shared__ float s_ws[2][4][10];
  int tid = threadIdx.x;
  for (int i = tid; i < 10000; i += 256) s_w[i] = fc2_w[i];
  if (tid < 10) s_b[tid] = fc2_b[tid];

  int r = tid >> 7, lane = tid & 127;
  int wip = (tid >> 5) & 3;              // warp index within row
  int b = blockIdx.x * 2 + r;

  const float* p0 = g_fc1p[0];
  const float* p1 = g_fc1p[1];
  const float* p2 = g_fc1p[2];
  const float* p3 = g_fc1p[3];

  float m1[8], c1[8];
#pragma unroll
  for (int u = 0; u < 8; u++) {
    int j = lane + 128 * u;
    if (j < 1000) {
      int idx = b * 1000 + j;
      float t = __fadd_rn(__fadd_rn(__fadd_rn(p0[idx], p1[idx]), p2[idx]),
                          p3[idx]);
      c1[u] = __fadd_rn(t, fc1_b[j]);
    } else {
      c1[u] = 0.f;
    }
    m1[u] = 0.f;
  }
  float mem2 = 0.f;
  __syncthreads();

  for (int t = 0; t < 10; t++) {
    float acc[10];
#pragma unroll
    for (int k = 0; k < 10; k++) acc[k] = 0.f;
#pragma unroll
    for (int u = 0; u < 8; u++) {
      int j = lane + 128 * u;
      // snnTorch Leaky: subtract-reset from PREVIOUS mem, then new spike
      float reset = (m1[u] > 1.0f) ? 1.0f : 0.0f;
      float nm = 0.95f * m1[u] + c1[u] - reset;
      m1[u] = nm;
      if (j < 1000 && nm > 1.0f) {
#pragma unroll
        for (int k = 0; k < 10; k++) acc[k] += s_w[k * 1000 + j];
      }
    }
#pragma unroll
    for (int k = 0; k < 10; k++) {
      float v = acc[k];
      v += __shfl_down_sync(0xffffffffu, v, 16);
      v += __shfl_down_sync(0xffffffffu, v, 8);
      v += __shfl_down_sync(0xffffffffu, v, 4);
      v += __shfl_down_sync(0xffffffffu, v, 2);
      v += __shfl_down_sync(0xffffffffu, v, 1);
      acc[k] = v;
    }
    if ((tid & 31) == 0) {
#pragma unroll
      for (int k = 0; k < 10; k++) s_ws[r][wip][k] = acc[k];
    }
    __syncthreads();
    if (lane < 10) {
      int k = lane;
      float cur2 = (((s_ws[r][0][k] + s_ws[r][1][k]) + s_ws[r][2][k]) +
                    s_ws[r][3][k]) + s_b[k];
      float reset2 = (mem2 > 1.0f) ? 1.0f : 0.0f;
      float nm2 = 0.95f * mem2 + cur2 - reset2;
      mem2 = nm2;
      float spk2 = (nm2 > 1.0f) ? 1.0f : 0.0f;
      out[t * 5120 + b * 10 + k] = spk2;
      out[51200 + t * 5120 + b * 10 + k] = nm2;
    }
    __syncthreads();
  }
}

// ================================= launcher ================================
extern "C" void kernel_launch(void* const* d_in, const int* in_sizes, int n_in,
                              void* d_out, int out_size) {
  const float* x   = (const float*)d_in[0];
  const float* c1w = (const float*)d_in[1];
  const float* c1b = (const float*)d_in[2];
  const float* c2w = (const float*)d_in[3];
  const float* c2b = (const float*)d_in[4];
  const float* f1w = (const float*)d_in[5];
  const float* f1b = (const float*)d_in[6];
  const float* f2w = (const float*)d_in[7];
  const float* f2b = (const float*)d_in[8];
  float* out = (float*)d_out;

  cudaFuncSetAttribute(conv2_kernel,
                       cudaFuncAttributeMaxDynamicSharedMemorySize, 115456);

  conv1_kernel<<<512, 256>>>(x, c1w, c1b);
  conv2_kernel<<<512, 256, 115456>>>(c2w, c2b);
  fc1_kernel<<<dim3(8, 4, 4), 256>>>(f1w);
  snn_kernel<<<256, 256>>>(f2w, f2b, f1b, out);
}